// round 4
// baseline (speedup 1.0000x reference)
#include <cuda_runtime.h>
#include <cuda_bf16.h>
#include <cstdint>

// ---------------------------------------------------------------------------
// Problem constants
// ---------------------------------------------------------------------------
#define BATCH   2
#define SEQ     3072
#define DMODEL  512
#define NHEADS  8
#define DHEAD   64
#define MROWS   (BATCH * SEQ)      // 6144
#define MAXNB   32
#define CAP     256

typedef unsigned long long u64;
typedef unsigned int u32;

// ---------------------------------------------------------------------------
// Scratch (static device memory; no allocations allowed)
// ---------------------------------------------------------------------------
__device__ float g_Q[MROWS * DMODEL];
__device__ float g_K[MROWS * DMODEL];
__device__ float g_V[MROWS * DMODEL];
__device__ int   g_nbr[MROWS * MAXNB];
__device__ int   g_cnt[MROWS];

// bf16 hi/lo splits
__device__ __nv_bfloat16 g_xh[MROWS * DMODEL];
__device__ __nv_bfloat16 g_xl[MROWS * DMODEL];
__device__ __nv_bfloat16 g_ah[MROWS * DMODEL];
__device__ __nv_bfloat16 g_al[MROWS * DMODEL];
// transposed weights [n][k], 4 matrices (q,k,v,o)
__device__ __nv_bfloat16 g_wth[4 * DMODEL * DMODEL];
__device__ __nv_bfloat16 g_wtl[4 * DMODEL * DMODEL];

// ---------------------------------------------------------------------------
// helpers
// ---------------------------------------------------------------------------
__device__ __forceinline__ u32 smem_u32(const void* p) {
    u32 a;
    asm("{ .reg .u64 t; cvta.to.shared.u64 t, %1; cvt.u32.u64 %0, t; }"
        : "=r"(a) : "l"(p));
    return a;
}

__device__ __forceinline__ void split1(float v, __nv_bfloat16& h, __nv_bfloat16& l) {
    h = __float2bfloat16(v);
    l = __float2bfloat16(v - __bfloat162float(h));
}

__global__ void __launch_bounds__(256)
split_x_kernel(const float* __restrict__ x)
{
    const int i = blockIdx.x * blockDim.x + threadIdx.x;   // float4 index
    const float4 v = ((const float4*)x)[i];
    __nv_bfloat16 h0, h1, h2, h3, l0, l1, l2, l3;
    split1(v.x, h0, l0); split1(v.y, h1, l1);
    split1(v.z, h2, l2); split1(v.w, h3, l3);
    __nv_bfloat162* hp = (__nv_bfloat162*)g_xh;
    __nv_bfloat162* lp = (__nv_bfloat162*)g_xl;
    hp[2 * i]     = __nv_bfloat162(h0, h1);
    hp[2 * i + 1] = __nv_bfloat162(h2, h3);
    lp[2 * i]     = __nv_bfloat162(l0, l1);
    lp[2 * i + 1] = __nv_bfloat162(l2, l3);
}

// W[k][n] -> Wt[n][k] hi/lo, 4 matrices via blockIdx.z
__global__ void __launch_bounds__(1024)
transpose_split_kernel(const float* __restrict__ Wq, const float* __restrict__ Wk,
                       const float* __restrict__ Wv, const float* __restrict__ Wo)
{
    __shared__ float t[32][33];
    const float* W = (blockIdx.z == 0) ? Wq : (blockIdx.z == 1) ? Wk
                   : (blockIdx.z == 2) ? Wv : Wo;
    __nv_bfloat16* Th = g_wth + blockIdx.z * DMODEL * DMODEL;
    __nv_bfloat16* Tl = g_wtl + blockIdx.z * DMODEL * DMODEL;

    const int n = blockIdx.x * 32 + threadIdx.x;
    const int k = blockIdx.y * 32 + threadIdx.y;
    t[threadIdx.y][threadIdx.x] = W[k * DMODEL + n];
    __syncthreads();
    const int no = blockIdx.x * 32 + threadIdx.y;
    const int ko = blockIdx.y * 32 + threadIdx.x;
    const float v = t[threadIdx.x][threadIdx.y];
    __nv_bfloat16 h, l; split1(v, h, l);
    Th[no * DMODEL + ko] = h;
    Tl[no * DMODEL + ko] = l;
}

// ---------------------------------------------------------------------------
// Tensor-core GEMM via mma.sync m16n8k16 bf16 + ldmatrix fragment loads.
// C = A @ Wt^T + bias, 3-term bf16 split (Ah*Bh + Al*Bh + Ah*Bl).
// CTA 128x128, BK=32, 8 warps (4M x 2N), warp tile 32x64.
// ---------------------------------------------------------------------------
#define ASTR 40    // smem row stride in bf16 (80B): rows hit disjoint bank sets

__device__ __forceinline__ void mma16816(float* c, const u32* a, u32 b0, u32 b1) {
    asm volatile(
        "mma.sync.aligned.m16n8k16.row.col.f32.bf16.bf16.f32 "
        "{%0,%1,%2,%3}, {%4,%5,%6,%7}, {%8,%9}, {%0,%1,%2,%3};"
        : "+f"(c[0]), "+f"(c[1]), "+f"(c[2]), "+f"(c[3])
        : "r"(a[0]), "r"(a[1]), "r"(a[2]), "r"(a[3]), "r"(b0), "r"(b1));
}

__device__ __forceinline__ void ldsm4(u32* r, u32 addr) {
    asm volatile("ldmatrix.sync.aligned.m8n8.x4.shared.b16 {%0,%1,%2,%3}, [%4];"
        : "=r"(r[0]), "=r"(r[1]), "=r"(r[2]), "=r"(r[3]) : "r"(addr));
}

__device__ __forceinline__ void tc_gemm_body(const __nv_bfloat16* __restrict__ Ah,
                                             const __nv_bfloat16* __restrict__ Al,
                                             const __nv_bfloat16* __restrict__ Bh,
                                             const __nv_bfloat16* __restrict__ Bl,
                                             const float* __restrict__ bias,
                                             float* __restrict__ C)
{
    __shared__ __nv_bfloat16 sAh[128 * ASTR];
    __shared__ __nv_bfloat16 sAl[128 * ASTR];
    __shared__ __nv_bfloat16 sBh[128 * ASTR];
    __shared__ __nv_bfloat16 sBl[128 * ASTR];

    const int tid  = threadIdx.x;
    const int w    = tid >> 5;
    const int lane = tid & 31;
    const int g    = lane >> 2;       // 0..7
    const int t2   = (lane & 3) * 2;  // 0,2,4,6
    const int wm   = w & 3;           // M warp (32 rows)
    const int wn   = w >> 2;          // N warp (64 cols)
    const int m0   = blockIdx.y * 128;
    const int n0   = blockIdx.x * 128;

    // global loader mapping: r=tid/4 (0..63, +64), seg=tid%4 (8 cols each)
    const int lr  = tid >> 2;
    const int lc  = (tid & 3) * 8;

    // ldmatrix lane address components
    const int lrow = lane & 15;
    const int lcol = (lane >> 4) * 8;
    const u32 aH = smem_u32(sAh) + ((wm * 32 + lrow) * ASTR + lcol) * 2;
    const u32 aL = smem_u32(sAl) + ((wm * 32 + lrow) * ASTR + lcol) * 2;
    const u32 bH = smem_u32(sBh) + ((wn * 64 + lrow) * ASTR + lcol) * 2;
    const u32 bL = smem_u32(sBl) + ((wn * 64 + lrow) * ASTR + lcol) * 2;

    float acc[2][8][4];
    #pragma unroll
    for (int i = 0; i < 2; ++i)
        #pragma unroll
        for (int j = 0; j < 8; ++j)
            #pragma unroll
            for (int q = 0; q < 4; ++q) acc[i][j][q] = 0.f;

    for (int kc = 0; kc < DMODEL / 32; ++kc) {
        const size_t eA0 = (size_t)(m0 + lr) * DMODEL + kc * 32 + lc;
        const size_t eA1 = eA0 + (size_t)64 * DMODEL;
        const size_t eB0 = (size_t)(n0 + lr) * DMODEL + kc * 32 + lc;
        const size_t eB1 = eB0 + (size_t)64 * DMODEL;
        const uint4 vah0 = *(const uint4*)(Ah + eA0);
        const uint4 vah1 = *(const uint4*)(Ah + eA1);
        const uint4 val0 = *(const uint4*)(Al + eA0);
        const uint4 val1 = *(const uint4*)(Al + eA1);
        const uint4 vbh0 = *(const uint4*)(Bh + eB0);
        const uint4 vbh1 = *(const uint4*)(Bh + eB1);
        const uint4 vbl0 = *(const uint4*)(Bl + eB0);
        const uint4 vbl1 = *(const uint4*)(Bl + eB1);

        __syncthreads();   // previous tile fully consumed
        *(uint4*)(sAh + lr * ASTR + lc)        = vah0;
        *(uint4*)(sAh + (lr + 64) * ASTR + lc) = vah1;
        *(uint4*)(sAl + lr * ASTR + lc)        = val0;
        *(uint4*)(sAl + (lr + 64) * ASTR + lc) = val1;
        *(uint4*)(sBh + lr * ASTR + lc)        = vbh0;
        *(uint4*)(sBh + (lr + 64) * ASTR + lc) = vbh1;
        *(uint4*)(sBl + lr * ASTR + lc)        = vbl0;
        *(uint4*)(sBl + (lr + 64) * ASTR + lc) = vbl1;
        __syncthreads();

        #pragma unroll
        for (int ks = 0; ks < 32; ks += 16) {
            u32 ah[2][4], al[2][4];
            #pragma unroll
            for (int ma = 0; ma < 2; ++ma) {
                ldsm4(ah[ma], aH + (ma * 16 * ASTR + ks) * 2);
                ldsm4(al[ma], aL + (ma * 16 * ASTR + ks) * 2);
            }
            #pragma unroll
            for (int i = 0; i < 4; ++i) {       // 16 n-rows per iter
                u32 bh[4], bl[4];
                ldsm4(bh, bH + (i * 16 * ASTR + ks) * 2);
                ldsm4(bl, bL + (i * 16 * ASTR + ks) * 2);
                #pragma unroll
                for (int sub = 0; sub < 2; ++sub) {
                    const int na = 2 * i + sub;
                    #pragma unroll
                    for (int ma = 0; ma < 2; ++ma) {
                        mma16816(acc[ma][na], ah[ma], bh[sub], bh[sub + 2]);
                        mma16816(acc[ma][na], al[ma], bh[sub], bh[sub + 2]);
                        mma16816(acc[ma][na], ah[ma], bl[sub], bl[sub + 2]);
                    }
                }
            }
        }
    }

    // epilogue
    #pragma unroll
    for (int ma = 0; ma < 2; ++ma) {
        const int row = m0 + wm * 32 + ma * 16 + g;
        #pragma unroll
        for (int na = 0; na < 8; ++na) {
            const int col = n0 + wn * 64 + na * 8 + t2;
            const float b0 = bias[col], b1 = bias[col + 1];
            float2 o0; o0.x = acc[ma][na][0] + b0; o0.y = acc[ma][na][1] + b1;
            float2 o1; o1.x = acc[ma][na][2] + b0; o1.y = acc[ma][na][3] + b1;
            *(float2*)(C + (size_t)row * DMODEL + col) = o0;
            *(float2*)(C + (size_t)(row + 8) * DMODEL + col) = o1;
        }
    }
}

__global__ void __launch_bounds__(256, 2)
gemm_qkv_kernel(const float* __restrict__ bq, const float* __restrict__ bk,
                const float* __restrict__ bv)
{
    const int z = blockIdx.z;
    const __nv_bfloat16* Bh = g_wth + (size_t)z * DMODEL * DMODEL;
    const __nv_bfloat16* Bl = g_wtl + (size_t)z * DMODEL * DMODEL;
    const float* bias = (z == 0) ? bq : (z == 1) ? bk : bv;
    float* C = (z == 0) ? g_Q : (z == 1) ? g_K : g_V;
    tc_gemm_body(g_xh, g_xl, Bh, Bl, bias, C);
}

__global__ void __launch_bounds__(256, 2)
gemm_out_kernel(const float* __restrict__ bo, float* __restrict__ out)
{
    const __nv_bfloat16* Bh = g_wth + (size_t)3 * DMODEL * DMODEL;
    const __nv_bfloat16* Bl = g_wtl + (size_t)3 * DMODEL * DMODEL;
    tc_gemm_body(g_ah, g_al, Bh, Bl, bo, out);
}

// ---------------------------------------------------------------------------
// Top-k neighbor selection (unchanged — known correct)
// ---------------------------------------------------------------------------
__global__ void __launch_bounds__(256)
topk_kernel(const float* __restrict__ positions)
{
    extern __shared__ float fsm[];
    float* px = fsm;
    float* py = fsm + SEQ;
    float* pz = fsm + 2 * SEQ;
    u64*  cand = (u64*)(fsm + 3 * SEQ);

    const int tid  = threadIdx.x;
    const int warp = tid >> 5;
    const int lane = tid & 31;
    const int r0   = blockIdx.x * 8;
    const int b    = r0 / SEQ;
    const int sbase = b * SEQ;

    for (int i = tid; i < SEQ; i += 256) {
        const float* p = positions + (size_t)(sbase + i) * 3;
        px[i] = p[0]; py[i] = p[1]; pz[i] = p[2];
    }
    __syncthreads();

    const int row = r0 + warp;
    const int si  = row - sbase;
    const float qx = px[si], qy = py[si], qz = pz[si];
    u64* mycand = cand + warp * CAP;

    int cnt = 0;
    for (int t = 0; t < SEQ / 32; ++t) {
        const int j = t * 32 + lane;
        const float dx = px[j] - qx, dy = py[j] - qy, dz = pz[j] - qz;
        const float dist = sqrtf(dx * dx + dy * dy + dz * dz);
        const bool in = dist < 0.5f;
        const unsigned msk = __ballot_sync(0xffffffffu, in);
        if (in) {
            const int pos = cnt + __popc(msk & ((1u << lane) - 1u));
            if (pos < CAP)
                mycand[pos] = ((u64)__float_as_uint(dist) << 32) | (unsigned)j;
        }
        cnt += __popc(msk);
    }
    if (cnt > CAP) cnt = CAP;
    __syncwarp();

    if (cnt <= MAXNB) {
        if (lane < cnt)
            g_nbr[row * MAXNB + lane] = sbase + (int)(mycand[lane] & 0xffffffffull);
        if (lane == 0) g_cnt[row] = cnt;
    } else {
        for (int sel = 0; sel < MAXNB; ++sel) {
            u64 best = ~0ull; int bslot = 0;
            for (int s2 = lane; s2 < cnt; s2 += 32) {
                const u64 kk = mycand[s2];
                if (kk < best) { best = kk; bslot = s2; }
            }
            #pragma unroll
            for (int off = 16; off; off >>= 1) {
                const u64 ob = __shfl_xor_sync(0xffffffffu, best, off);
                const int os = __shfl_xor_sync(0xffffffffu, bslot, off);
                if (ob < best) { best = ob; bslot = os; }
            }
            if (lane == 0) {
                g_nbr[row * MAXNB + sel] = sbase + (int)(best & 0xffffffffull);
                mycand[bslot] = ~0ull;
            }
            __syncwarp();
        }
        if (lane == 0) g_cnt[row] = MAXNB;
    }
}

// ---------------------------------------------------------------------------
// Sparse attention, restructured:
//  - K rows staged into smem coalescedly (256 thr x float2 per 2KB row)
//  - scores from padded smem (stride DMODEL+4)
//  - V streamed coalescedly; thread owns 2 output dims
//  - output split to bf16 hi/lo fused into epilogue
// ---------------------------------------------------------------------------
#define KSTR (DMODEL + 4)
#define ATTN_SMEM ((MAXNB * KSTR + NHEADS * DHEAD + NHEADS * MAXNB + MAXNB) * 4)

__global__ void __launch_bounds__(256)
attn_kernel()
{
    extern __shared__ float asm_[];
    float* sK   = asm_;                          // [MAXNB][KSTR]
    float* s_q  = sK + MAXNB * KSTR;             // [NHEADS][DHEAD]
    float* s_p  = s_q + NHEADS * DHEAD;          // [NHEADS][MAXNB]
    int*   s_nbr = (int*)(s_p + NHEADS * MAXNB); // [MAXNB]

    const int row  = blockIdx.x;
    const int tid  = threadIdx.x;
    const int h    = tid >> 5;
    const int lane = tid & 31;
    const int m    = g_cnt[row];

    if (tid < MAXNB)
        s_nbr[tid] = (tid < m) ? g_nbr[row * MAXNB + tid] : 0;

    const float2 q2 = *(const float2*)&g_Q[(size_t)row * DMODEL + h * DHEAD + lane * 2];
    *(float2*)&s_q[h * DHEAD + lane * 2] = q2;
    __syncthreads();

    // stage K rows (coalesced: whole 2KB row per j)
    #pragma unroll 4
    for (int j = 0; j < MAXNB; ++j) {
        if (j < m) {
            const float2 v = *(const float2*)&g_K[(size_t)s_nbr[j] * DMODEL + 2 * tid];
            *(float2*)&sK[j * KSTR + 2 * tid] = v;
        }
    }
    __syncthreads();

    // scores: warp = head, lane = neighbor
    float score = __int_as_float(0xff800000);
    if (lane < m) {
        const float4* kp = (const float4*)&sK[lane * KSTR + h * DHEAD];
        const float4* qp = (const float4*)&s_q[h * DHEAD];
        float acc = 0.f;
        #pragma unroll
        for (int c = 0; c < DHEAD / 4; ++c) {
            const float4 kv = kp[c];
            const float4 qv = qp[c];
            acc += kv.x * qv.x + kv.y * qv.y + kv.z * qv.z + kv.w * qv.w;
        }
        score = acc * 0.125f;
    }

    float mx = score;
    #pragma unroll
    for (int off = 16; off; off >>= 1)
        mx = fmaxf(mx, __shfl_xor_sync(0xffffffffu, mx, off));
    float p = __expf(score - mx);
    float sm = p;
    #pragma unroll
    for (int off = 16; off; off >>= 1)
        sm += __shfl_xor_sync(0xffffffffu, sm, off);
    s_p[h * MAXNB + lane] = p / sm;
    __syncthreads();

    // AV: thread owns dims (2*tid, 2*tid+1); head h = tid>>5 consistent
    float ox = 0.f, oy = 0.f;
    #pragma unroll 8
    for (int j = 0; j < MAXNB; ++j) {
        if (j < m) {
            const float pj = s_p[h * MAXNB + j];
            const float2 v2 = *(const float2*)&g_V[(size_t)s_nbr[j] * DMODEL + 2 * tid];
            ox += pj * v2.x;
            oy += pj * v2.y;
        }
    }

    // fused bf16 hi/lo split of attention output
    __nv_bfloat16 h0, l0, h1, l1;
    split1(ox, h0, l0);
    split1(oy, h1, l1);
    *(__nv_bfloat162*)&g_ah[(size_t)row * DMODEL + 2 * tid] = __nv_bfloat162(h0, h1);
    *(__nv_bfloat162*)&g_al[(size_t)row * DMODEL + 2 * tid] = __nv_bfloat162(l0, l1);
}

// ---------------------------------------------------------------------------
// Launch
// ---------------------------------------------------------------------------
extern "C" void kernel_launch(void* const* d_in, const int* in_sizes, int n_in,
                              void* d_out, int out_size)
{
    (void)in_sizes; (void)n_in; (void)out_size;
    const float* x   = (const float*)d_in[0];
    const float* pos = (const float*)d_in[1];
    const float* Wq  = (const float*)d_in[2];
    const float* bq  = (const float*)d_in[3];
    const float* Wk  = (const float*)d_in[4];
    const float* bk  = (const float*)d_in[5];
    const float* Wv  = (const float*)d_in[6];
    const float* bv  = (const float*)d_in[7];
    const float* Wo  = (const float*)d_in[8];
    const float* bo  = (const float*)d_in[9];
    float* out = (float*)d_out;

    const int topk_smem = 3 * SEQ * 4 + 8 * CAP * 8;
    cudaFuncSetAttribute(topk_kernel,
                         cudaFuncAttributeMaxDynamicSharedMemorySize, topk_smem);
    cudaFuncSetAttribute(attn_kernel,
                         cudaFuncAttributeMaxDynamicSharedMemorySize, ATTN_SMEM);

    topk_kernel<<<MROWS / 8, 256, topk_smem>>>(pos);
    transpose_split_kernel<<<dim3(16, 16, 4), dim3(32, 32)>>>(Wq, Wk, Wv, Wo);
    split_x_kernel<<<(MROWS * DMODEL / 4) / 256, 256>>>(x);
    gemm_qkv_kernel<<<dim3(DMODEL / 128, MROWS / 128, 3), 256>>>(bq, bk, bv);
    attn_kernel<<<MROWS, 256, ATTN_SMEM>>>();
    gemm_out_kernel<<<dim3(DMODEL / 128, MROWS / 128, 1), 256>>>(bo, out);
}

// round 5
// speedup vs baseline: 1.0056x; 1.0056x over previous
#include <cuda_runtime.h>
#include <cuda_bf16.h>
#include <cstdint>

// ---------------------------------------------------------------------------
// Problem constants
// ---------------------------------------------------------------------------
#define BATCH   2
#define SEQ     3072
#define DMODEL  512
#define NHEADS  8
#define DHEAD   64
#define MROWS   (BATCH * SEQ)      // 6144
#define MAXNB   32
#define CAP     256

typedef unsigned long long u64;
typedef unsigned int u32;

// ---------------------------------------------------------------------------
// Scratch (static device memory; no allocations allowed)
// ---------------------------------------------------------------------------
__device__ float g_Q[MROWS * DMODEL];
__device__ float g_K[MROWS * DMODEL];
__device__ float g_V[MROWS * DMODEL];
__device__ int   g_nbr[MROWS * MAXNB];
__device__ int   g_cnt[MROWS];

// bf16 hi/lo splits
__device__ __nv_bfloat16 g_xh[MROWS * DMODEL];
__device__ __nv_bfloat16 g_xl[MROWS * DMODEL];
__device__ __nv_bfloat16 g_ah[MROWS * DMODEL];
__device__ __nv_bfloat16 g_al[MROWS * DMODEL];
// transposed weights [n][k], 4 matrices (q,k,v,o)
__device__ __nv_bfloat16 g_wth[4 * DMODEL * DMODEL];
__device__ __nv_bfloat16 g_wtl[4 * DMODEL * DMODEL];

// ---------------------------------------------------------------------------
// helpers
// ---------------------------------------------------------------------------
__device__ __forceinline__ u32 smem_u32(const void* p) {
    u32 a;
    asm("{ .reg .u64 t; cvta.to.shared.u64 t, %1; cvt.u32.u64 %0, t; }"
        : "=r"(a) : "l"(p));
    return a;
}

__device__ __forceinline__ void split1(float v, __nv_bfloat16& h, __nv_bfloat16& l) {
    h = __float2bfloat16(v);
    l = __float2bfloat16(v - __bfloat162float(h));
}

__global__ void __launch_bounds__(256)
split_x_kernel(const float* __restrict__ x)
{
    const int i = blockIdx.x * blockDim.x + threadIdx.x;   // float4 index
    const float4 v = ((const float4*)x)[i];
    __nv_bfloat16 h0, h1, h2, h3, l0, l1, l2, l3;
    split1(v.x, h0, l0); split1(v.y, h1, l1);
    split1(v.z, h2, l2); split1(v.w, h3, l3);
    __nv_bfloat162* hp = (__nv_bfloat162*)g_xh;
    __nv_bfloat162* lp = (__nv_bfloat162*)g_xl;
    hp[2 * i]     = __nv_bfloat162(h0, h1);
    hp[2 * i + 1] = __nv_bfloat162(h2, h3);
    lp[2 * i]     = __nv_bfloat162(l0, l1);
    lp[2 * i + 1] = __nv_bfloat162(l2, l3);
}

// W[k][n] -> Wt[n][k] hi/lo, 4 matrices via blockIdx.z
__global__ void __launch_bounds__(1024)
transpose_split_kernel(const float* __restrict__ Wq, const float* __restrict__ Wk,
                       const float* __restrict__ Wv, const float* __restrict__ Wo)
{
    __shared__ float t[32][33];
    const float* W = (blockIdx.z == 0) ? Wq : (blockIdx.z == 1) ? Wk
                   : (blockIdx.z == 2) ? Wv : Wo;
    __nv_bfloat16* Th = g_wth + blockIdx.z * DMODEL * DMODEL;
    __nv_bfloat16* Tl = g_wtl + blockIdx.z * DMODEL * DMODEL;

    const int n = blockIdx.x * 32 + threadIdx.x;
    const int k = blockIdx.y * 32 + threadIdx.y;
    t[threadIdx.y][threadIdx.x] = W[k * DMODEL + n];
    __syncthreads();
    const int no = blockIdx.x * 32 + threadIdx.y;
    const int ko = blockIdx.y * 32 + threadIdx.x;
    const float v = t[threadIdx.x][threadIdx.y];
    __nv_bfloat16 h, l; split1(v, h, l);
    Th[no * DMODEL + ko] = h;
    Tl[no * DMODEL + ko] = l;
}

// ---------------------------------------------------------------------------
// Tensor-core GEMM, software-pipelined with double-buffered dynamic smem.
// C = A @ Wt^T + bias, 3-term bf16 split (Ah*Bh + Al*Bh + Ah*Bl).
// CTA 128x128, BK=32, 8 warps (4M x 2N), warp tile 32x64.
// Loop: LDG(kc+1) -> MMA(kc) -> STS(kc+1) -> sync   (one sync / iter,
// LDG->STS gap bridged by 96 MMAs).
// ---------------------------------------------------------------------------
#define ASTR 40                    // smem row stride in bf16 (80B)
#define TILE_E (128 * ASTR)        // elems per matrix tile
#define BUF_E  (4 * TILE_E)        // elems per buffer (Ah,Al,Bh,Bl)
#define GEMM_SMEM (2 * BUF_E * 2)  // bytes (81920)

__device__ __forceinline__ void mma16816(float* c, const u32* a, u32 b0, u32 b1) {
    asm volatile(
        "mma.sync.aligned.m16n8k16.row.col.f32.bf16.bf16.f32 "
        "{%0,%1,%2,%3}, {%4,%5,%6,%7}, {%8,%9}, {%0,%1,%2,%3};"
        : "+f"(c[0]), "+f"(c[1]), "+f"(c[2]), "+f"(c[3])
        : "r"(a[0]), "r"(a[1]), "r"(a[2]), "r"(a[3]), "r"(b0), "r"(b1));
}

__device__ __forceinline__ void ldsm4(u32* r, u32 addr) {
    asm volatile("ldmatrix.sync.aligned.m8n8.x4.shared.b16 {%0,%1,%2,%3}, [%4];"
        : "=r"(r[0]), "=r"(r[1]), "=r"(r[2]), "=r"(r[3]) : "r"(addr));
}

__device__ __forceinline__ void tc_gemm_body(const __nv_bfloat16* __restrict__ Ah,
                                             const __nv_bfloat16* __restrict__ Al,
                                             const __nv_bfloat16* __restrict__ Bh,
                                             const __nv_bfloat16* __restrict__ Bl,
                                             const float* __restrict__ bias,
                                             float* __restrict__ C)
{
    extern __shared__ __nv_bfloat16 dsm[];   // [2][4][TILE_E]

    const int tid  = threadIdx.x;
    const int w    = tid >> 5;
    const int lane = tid & 31;
    const int g    = lane >> 2;       // 0..7
    const int t2   = (lane & 3) * 2;  // 0,2,4,6
    const int wm   = w & 3;           // M warp (32 rows)
    const int wn   = w >> 2;          // N warp (64 cols)
    const int m0   = blockIdx.y * 128;
    const int n0   = blockIdx.x * 128;

    // global loader mapping: r=tid/4 (0..63, +64), seg=tid%4 (8 cols each)
    const int lr  = tid >> 2;
    const int lc  = (tid & 3) * 8;

    // ldmatrix lane address components (buffer 0)
    const int lrow = lane & 15;
    const int lcol = (lane >> 4) * 8;
    const u32 sbase = smem_u32(dsm);
    const u32 aH0 = sbase + ((wm * 32 + lrow) * ASTR + lcol) * 2;
    const u32 aL0 = aH0 + TILE_E * 2;
    const u32 bH0 = sbase + (2 * TILE_E + (wn * 64 + lrow) * ASTR + lcol) * 2;
    const u32 bL0 = bH0 + TILE_E * 2;

    float acc[2][8][4];
    #pragma unroll
    for (int i = 0; i < 2; ++i)
        #pragma unroll
        for (int j = 0; j < 8; ++j)
            #pragma unroll
            for (int q = 0; q < 4; ++q) acc[i][j][q] = 0.f;

    uint4 rg[8];
    const size_t oA0 = (size_t)(m0 + lr) * DMODEL + lc;
    const size_t oA1 = oA0 + (size_t)64 * DMODEL;
    const size_t oB0 = (size_t)(n0 + lr) * DMODEL + lc;
    const size_t oB1 = oB0 + (size_t)64 * DMODEL;

    // ---- preload tile 0
    {
        rg[0] = *(const uint4*)(Ah + oA0); rg[1] = *(const uint4*)(Ah + oA1);
        rg[2] = *(const uint4*)(Al + oA0); rg[3] = *(const uint4*)(Al + oA1);
        rg[4] = *(const uint4*)(Bh + oB0); rg[5] = *(const uint4*)(Bh + oB1);
        rg[6] = *(const uint4*)(Bl + oB0); rg[7] = *(const uint4*)(Bl + oB1);
        __nv_bfloat16* s = dsm;
        *(uint4*)(s + lr * ASTR + lc)                       = rg[0];
        *(uint4*)(s + (lr + 64) * ASTR + lc)                = rg[1];
        *(uint4*)(s + TILE_E + lr * ASTR + lc)              = rg[2];
        *(uint4*)(s + TILE_E + (lr + 64) * ASTR + lc)       = rg[3];
        *(uint4*)(s + 2 * TILE_E + lr * ASTR + lc)          = rg[4];
        *(uint4*)(s + 2 * TILE_E + (lr + 64) * ASTR + lc)   = rg[5];
        *(uint4*)(s + 3 * TILE_E + lr * ASTR + lc)          = rg[6];
        *(uint4*)(s + 3 * TILE_E + (lr + 64) * ASTR + lc)   = rg[7];
    }
    __syncthreads();

    for (int kc = 0; kc < DMODEL / 32; ++kc) {
        const int cur = kc & 1;
        const bool more = (kc + 1) < DMODEL / 32;

        // LDG next tile (latency covered by MMAs below)
        if (more) {
            const size_t ko = (size_t)(kc + 1) * 32;
            rg[0] = *(const uint4*)(Ah + oA0 + ko); rg[1] = *(const uint4*)(Ah + oA1 + ko);
            rg[2] = *(const uint4*)(Al + oA0 + ko); rg[3] = *(const uint4*)(Al + oA1 + ko);
            rg[4] = *(const uint4*)(Bh + oB0 + ko); rg[5] = *(const uint4*)(Bh + oB1 + ko);
            rg[6] = *(const uint4*)(Bl + oB0 + ko); rg[7] = *(const uint4*)(Bl + oB1 + ko);
        }

        // MMA on current buffer
        const u32 bufo = cur * (BUF_E * 2);
        const u32 aH = aH0 + bufo, aL = aL0 + bufo;
        const u32 bH = bH0 + bufo, bL = bL0 + bufo;
        #pragma unroll
        for (int ks = 0; ks < 32; ks += 16) {
            u32 ah[2][4], al[2][4];
            #pragma unroll
            for (int ma = 0; ma < 2; ++ma) {
                ldsm4(ah[ma], aH + (ma * 16 * ASTR + ks) * 2);
                ldsm4(al[ma], aL + (ma * 16 * ASTR + ks) * 2);
            }
            #pragma unroll
            for (int i = 0; i < 4; ++i) {       // 16 n-rows per iter
                u32 bh[4], bl[4];
                ldsm4(bh, bH + (i * 16 * ASTR + ks) * 2);
                ldsm4(bl, bL + (i * 16 * ASTR + ks) * 2);
                #pragma unroll
                for (int sub = 0; sub < 2; ++sub) {
                    const int na = 2 * i + sub;
                    #pragma unroll
                    for (int ma = 0; ma < 2; ++ma) {
                        mma16816(acc[ma][na], ah[ma], bh[sub], bh[sub + 2]);
                        mma16816(acc[ma][na], al[ma], bh[sub], bh[sub + 2]);
                        mma16816(acc[ma][na], ah[ma], bl[sub], bl[sub + 2]);
                    }
                }
            }
        }

        // STS next tile into other buffer
        if (more) {
            __nv_bfloat16* s = dsm + (cur ^ 1) * BUF_E;
            *(uint4*)(s + lr * ASTR + lc)                       = rg[0];
            *(uint4*)(s + (lr + 64) * ASTR + lc)                = rg[1];
            *(uint4*)(s + TILE_E + lr * ASTR + lc)              = rg[2];
            *(uint4*)(s + TILE_E + (lr + 64) * ASTR + lc)       = rg[3];
            *(uint4*)(s + 2 * TILE_E + lr * ASTR + lc)          = rg[4];
            *(uint4*)(s + 2 * TILE_E + (lr + 64) * ASTR + lc)   = rg[5];
            *(uint4*)(s + 3 * TILE_E + lr * ASTR + lc)          = rg[6];
            *(uint4*)(s + 3 * TILE_E + (lr + 64) * ASTR + lc)   = rg[7];
        }
        __syncthreads();
    }

    // epilogue
    #pragma unroll
    for (int ma = 0; ma < 2; ++ma) {
        const int row = m0 + wm * 32 + ma * 16 + g;
        #pragma unroll
        for (int na = 0; na < 8; ++na) {
            const int col = n0 + wn * 64 + na * 8 + t2;
            const float b0 = bias[col], b1 = bias[col + 1];
            float2 o0; o0.x = acc[ma][na][0] + b0; o0.y = acc[ma][na][1] + b1;
            float2 o1; o1.x = acc[ma][na][2] + b0; o1.y = acc[ma][na][3] + b1;
            *(float2*)(C + (size_t)row * DMODEL + col) = o0;
            *(float2*)(C + (size_t)(row + 8) * DMODEL + col) = o1;
        }
    }
}

__global__ void __launch_bounds__(256, 2)
gemm_qkv_kernel(const float* __restrict__ bq, const float* __restrict__ bk,
                const float* __restrict__ bv)
{
    const int z = blockIdx.z;
    const __nv_bfloat16* Bh = g_wth + (size_t)z * DMODEL * DMODEL;
    const __nv_bfloat16* Bl = g_wtl + (size_t)z * DMODEL * DMODEL;
    const float* bias = (z == 0) ? bq : (z == 1) ? bk : bv;
    float* C = (z == 0) ? g_Q : (z == 1) ? g_K : g_V;
    tc_gemm_body(g_xh, g_xl, Bh, Bl, bias, C);
}

__global__ void __launch_bounds__(256, 2)
gemm_out_kernel(const float* __restrict__ bo, float* __restrict__ out)
{
    const __nv_bfloat16* Bh = g_wth + (size_t)3 * DMODEL * DMODEL;
    const __nv_bfloat16* Bl = g_wtl + (size_t)3 * DMODEL * DMODEL;
    tc_gemm_body(g_ah, g_al, Bh, Bl, bo, out);
}

// ---------------------------------------------------------------------------
// Top-k neighbor selection (unchanged — known correct)
// ---------------------------------------------------------------------------
__global__ void __launch_bounds__(256)
topk_kernel(const float* __restrict__ positions)
{
    extern __shared__ float fsm[];
    float* px = fsm;
    float* py = fsm + SEQ;
    float* pz = fsm + 2 * SEQ;
    u64*  cand = (u64*)(fsm + 3 * SEQ);

    const int tid  = threadIdx.x;
    const int warp = tid >> 5;
    const int lane = tid & 31;
    const int r0   = blockIdx.x * 8;
    const int b    = r0 / SEQ;
    const int sbase = b * SEQ;

    for (int i = tid; i < SEQ; i += 256) {
        const float* p = positions + (size_t)(sbase + i) * 3;
        px[i] = p[0]; py[i] = p[1]; pz[i] = p[2];
    }
    __syncthreads();

    const int row = r0 + warp;
    const int si  = row - sbase;
    const float qx = px[si], qy = py[si], qz = pz[si];
    u64* mycand = cand + warp * CAP;

    int cnt = 0;
    for (int t = 0; t < SEQ / 32; ++t) {
        const int j = t * 32 + lane;
        const float dx = px[j] - qx, dy = py[j] - qy, dz = pz[j] - qz;
        const float dist = sqrtf(dx * dx + dy * dy + dz * dz);
        const bool in = dist < 0.5f;
        const unsigned msk = __ballot_sync(0xffffffffu, in);
        if (in) {
            const int pos = cnt + __popc(msk & ((1u << lane) - 1u));
            if (pos < CAP)
                mycand[pos] = ((u64)__float_as_uint(dist) << 32) | (unsigned)j;
        }
        cnt += __popc(msk);
    }
    if (cnt > CAP) cnt = CAP;
    __syncwarp();

    if (cnt <= MAXNB) {
        if (lane < cnt)
            g_nbr[row * MAXNB + lane] = sbase + (int)(mycand[lane] & 0xffffffffull);
        if (lane == 0) g_cnt[row] = cnt;
    } else {
        for (int sel = 0; sel < MAXNB; ++sel) {
            u64 best = ~0ull; int bslot = 0;
            for (int s2 = lane; s2 < cnt; s2 += 32) {
                const u64 kk = mycand[s2];
                if (kk < best) { best = kk; bslot = s2; }
            }
            #pragma unroll
            for (int off = 16; off; off >>= 1) {
                const u64 ob = __shfl_xor_sync(0xffffffffu, best, off);
                const int os = __shfl_xor_sync(0xffffffffu, bslot, off);
                if (ob < best) { best = ob; bslot = os; }
            }
            if (lane == 0) {
                g_nbr[row * MAXNB + sel] = sbase + (int)(best & 0xffffffffull);
                mycand[bslot] = ~0ull;
            }
            __syncwarp();
        }
        if (lane == 0) g_cnt[row] = MAXNB;
    }
}

// ---------------------------------------------------------------------------
// Sparse attention — R3 structure (fastest measured) + fused hi/lo split.
// One CTA per query row, warp = head, lane = neighbor for QK;
// AV via shfl broadcast, lane owns 2 output dims.
// ---------------------------------------------------------------------------
__global__ void __launch_bounds__(256)
attn_kernel()
{
    const int row = blockIdx.x;
    __shared__ int   s_nbr[MAXNB];
    __shared__ float s_q[NHEADS][DHEAD];

    const int tid  = threadIdx.x;
    const int h    = tid >> 5;
    const int lane = tid & 31;
    const int m    = g_cnt[row];

    if (tid < MAXNB)
        s_nbr[tid] = (tid < m) ? g_nbr[row * MAXNB + tid] : 0;

    const float2 q2 = *(const float2*)&g_Q[(size_t)row * DMODEL + h * DHEAD + lane * 2];
    ((float2*)s_q[h])[lane] = q2;
    __syncthreads();

    float score = __int_as_float(0xff800000);
    if (lane < m) {
        const float4* kp = (const float4*)&g_K[(size_t)s_nbr[lane] * DMODEL + h * DHEAD];
        const float4* qp = (const float4*)&s_q[h][0];
        float acc = 0.f;
        #pragma unroll
        for (int c = 0; c < DHEAD / 4; ++c) {
            const float4 kv = kp[c];
            const float4 qv = qp[c];
            acc += kv.x * qv.x + kv.y * qv.y + kv.z * qv.z + kv.w * qv.w;
        }
        score = acc * 0.125f;
    }

    float mx = score;
    #pragma unroll
    for (int off = 16; off; off >>= 1)
        mx = fmaxf(mx, __shfl_xor_sync(0xffffffffu, mx, off));
    float p = __expf(score - mx);
    float sm = p;
    #pragma unroll
    for (int off = 16; off; off >>= 1)
        sm += __shfl_xor_sync(0xffffffffu, sm, off);
    const float pn = p / sm;

    float ox = 0.f, oy = 0.f;
    #pragma unroll
    for (int j = 0; j < MAXNB; ++j) {
        const float pj = __shfl_sync(0xffffffffu, pn, j);
        if (j < m) {
            const float2 v2 =
                *(const float2*)&g_V[(size_t)s_nbr[j] * DMODEL + h * DHEAD + lane * 2];
            ox += pj * v2.x;
            oy += pj * v2.y;
        }
    }

    // fused bf16 hi/lo split of attention output (feeds gemm_out directly)
    __nv_bfloat16 h0, l0, h1, l1;
    split1(ox, h0, l0);
    split1(oy, h1, l1);
    const size_t oidx = (size_t)row * DMODEL + h * DHEAD + lane * 2;
    *(__nv_bfloat162*)&g_ah[oidx] = __nv_bfloat162(h0, h1);
    *(__nv_bfloat162*)&g_al[oidx] = __nv_bfloat162(l0, l1);
}

// ---------------------------------------------------------------------------
// Launch
// ---------------------------------------------------------------------------
extern "C" void kernel_launch(void* const* d_in, const int* in_sizes, int n_in,
                              void* d_out, int out_size)
{
    (void)in_sizes; (void)n_in; (void)out_size;
    const float* x   = (const float*)d_in[0];
    const float* pos = (const float*)d_in[1];
    const float* Wq  = (const float*)d_in[2];
    const float* bq  = (const float*)d_in[3];
    const float* Wk  = (const float*)d_in[4];
    const float* bk  = (const float*)d_in[5];
    const float* Wv  = (const float*)d_in[6];
    const float* bv  = (const float*)d_in[7];
    const float* Wo  = (const float*)d_in[8];
    const float* bo  = (const float*)d_in[9];
    float* out = (float*)d_out;

    const int topk_smem = 3 * SEQ * 4 + 8 * CAP * 8;
    cudaFuncSetAttribute(topk_kernel,
                         cudaFuncAttributeMaxDynamicSharedMemorySize, topk_smem);
    cudaFuncSetAttribute(gemm_qkv_kernel,
                         cudaFuncAttributeMaxDynamicSharedMemorySize, GEMM_SMEM);
    cudaFuncSetAttribute(gemm_out_kernel,
                         cudaFuncAttributeMaxDynamicSharedMemorySize, GEMM_SMEM);

    topk_kernel<<<MROWS / 8, 256, topk_smem>>>(pos);
    transpose_split_kernel<<<dim3(16, 16, 4), dim3(32, 32)>>>(Wq, Wk, Wv, Wo);
    split_x_kernel<<<(MROWS * DMODEL / 4) / 256, 256>>>(x);
    gemm_qkv_kernel<<<dim3(DMODEL / 128, MROWS / 128, 3), 256, GEMM_SMEM>>>(bq, bk, bv);
    attn_kernel<<<MROWS, 256>>>();
    gemm_out_kernel<<<dim3(DMODEL / 128, MROWS / 128, 1), 256, GEMM_SMEM>>>(bo, out);
}